// round 12
// baseline (speedup 1.0000x reference)
#include <cuda_runtime.h>
#include <math.h>

// Problem constants
#define BB 32
#define TT 1000
#define DD 640
#define VV 1024
#define NB 128    // CTAs (<= 148 SMs -> all co-resident, sw grid barrier safe)
#define NT 1024   // 32 warps per CTA; launch_bounds forces <=64 regs/thread

typedef unsigned long long u64;

// ---------------- persistent device state (no allocations allowed) ----------
__device__ __align__(16) float g_hbuf[2][BB][DD];   // double-buffered h
__device__ __align__(16) float g_c[BB][DD];
__device__ __align__(16) float g_z[BB][DD];
__device__ __align__(16) float4 g_part[BB][NB];     // (max, sumexp, argmax, -) per CTA
__device__ float g_score[BB];
__device__ u64   g_bar = 0ull;                      // monotone barrier counter

// ---------------- grid barrier (counting, no reset; deterministic count per
// launch so graph replays stay consistent) ----------------------------------
__device__ __forceinline__ void grid_barrier() {
    __syncthreads();
    if (threadIdx.x == 0) {
        __threadfence();
        u64 m = atomicAdd(&g_bar, 1ull) + 1ull;
        u64 goal = ((m + (u64)NB - 1ull) / (u64)NB) * (u64)NB;
        while (*((volatile u64*)&g_bar) < goal) { }
        __threadfence();
    }
    __syncthreads();
}

__device__ __forceinline__ float wred(float v) {
    v += __shfl_xor_sync(0xffffffffu, v, 16);
    v += __shfl_xor_sync(0xffffffffu, v, 8);
    v += __shfl_xor_sync(0xffffffffu, v, 4);
    v += __shfl_xor_sync(0xffffffffu, v, 2);
    v += __shfl_xor_sync(0xffffffffu, v, 1);
    return v;
}

__device__ __forceinline__ float sigf(float x) { return 1.0f / (1.0f + expf(-x)); }

// Order-independent logsumexp/argmax merge (first-index on exact ties).
__device__ __forceinline__ void pmerge(float& m, float& s, int& mi,
                                       float m2, float s2, int i2) {
    if (m2 > m || (m2 == m && i2 < mi)) {
        s = s2 + s * expf(m - m2);
        m = m2; mi = i2;
    } else {
        s = s + s2 * expf(m2 - m);
    }
}

// ============================================================================
// Phase Z (term-split): warps 0-15 -> tn[b][t]·W_tn[j0..j0+4]
//                       warps 16-31 -> h[b]·W_pn[j0..j0+4]
// Each warp: 2 batches, 5 j, full K. Partials parked in smem zp[term].
// ============================================================================
__device__ __forceinline__ void z_phase(
    int cc, int wid, int lane, int t, int par,
    const float* __restrict__ tn, const float* __restrict__ W_tn,
    const float* __restrict__ W_pn, float zp[2][BB][5])
{
    const int j0   = cc * 5;
    const int term = wid >> 4;
    const int b0   = (wid & 15) * 2;
    const float* __restrict__ W = term ? W_pn : W_tn;

    float acc[2][5];
#pragma unroll
    for (int i = 0; i < 2; i++)
#pragma unroll
        for (int j = 0; j < 5; j++) acc[i][j] = 0.f;

    for (int kc = 0; kc < DD; kc += 128) {
        const int k = kc + lane * 4;
        float4 av[2];
#pragma unroll
        for (int i = 0; i < 2; i++) {
            av[i] = term
                ? *(const float4*)(&g_hbuf[par][b0 + i][k])
                : *(const float4*)(tn + ((size_t)(b0 + i) * TT + (size_t)t) * DD + k);
        }
#pragma unroll
        for (int j = 0; j < 5; j++) {
            float4 w = *(const float4*)(W + (size_t)(j0 + j) * DD + k);
#pragma unroll
            for (int i = 0; i < 2; i++) {
                float a = acc[i][j];
                a = fmaf(av[i].x, w.x, a); a = fmaf(av[i].y, w.y, a);
                a = fmaf(av[i].z, w.z, a); a = fmaf(av[i].w, w.w, a);
                acc[i][j] = a;
            }
        }
    }
#pragma unroll
    for (int i = 0; i < 2; i++)
#pragma unroll
        for (int j = 0; j < 5; j++) {
            float r = wred(acc[i][j]);
            if (lane == 0) zp[term][b0 + i][j] = r;
        }
}

// Z combine: 160 threads -> z = tanh(zpA + zpB + bias), write global g_z.
__device__ __forceinline__ void z_combine(
    int cc, int tid, const float* __restrict__ b_joint, float zp[2][BB][5])
{
    if (tid < BB * 5) {
        const int b = tid / 5, jj = tid - b * 5;
        const int j = cc * 5 + jj;
        g_z[b][j] = tanhf(zp[0][b][jj] + zp[1][b][jj] + b_joint[j]);
    }
}

// ============================================================================
// Phase L (v-split): warp owns 2 batches x 4 of the CTA's 8 v-columns, full K.
// Results to smem lv[b][8]; combine does 8-wide shuffle argmax/logsumexp.
// ============================================================================
__device__ __forceinline__ void l_phase(
    int cc, int wid, int lane,
    const float* __restrict__ W_out, float lv[BB][8])
{
    const int vh = wid >> 4;            // which half of the 8 columns
    const int b0 = (wid & 15) * 2;
    const int v0 = cc * 8 + vh * 4;

    float acc[2][4];
#pragma unroll
    for (int i = 0; i < 2; i++)
#pragma unroll
        for (int v = 0; v < 4; v++) acc[i][v] = 0.f;

    for (int kc = 0; kc < DD; kc += 128) {
        const int k = kc + lane * 4;
        float4 zv[2];
#pragma unroll
        for (int i = 0; i < 2; i++) zv[i] = *(const float4*)(&g_z[b0 + i][k]);
#pragma unroll
        for (int v = 0; v < 4; v++) {
            float4 w = *(const float4*)(W_out + (size_t)(v0 + v) * DD + k);
#pragma unroll
            for (int i = 0; i < 2; i++) {
                float a = acc[i][v];
                a = fmaf(zv[i].x, w.x, a); a = fmaf(zv[i].y, w.y, a);
                a = fmaf(zv[i].z, w.z, a); a = fmaf(zv[i].w, w.w, a);
                acc[i][v] = a;
            }
        }
    }
#pragma unroll
    for (int i = 0; i < 2; i++)
#pragma unroll
        for (int v = 0; v < 4; v++) {
            float r = wred(acc[i][v]);
            if (lane == 0) lv[b0 + i][vh * 4 + v] = r;
        }
}

// L combine: threads 0-255, thread = (b = tid/8, vs = tid%8); 8-wide shuffle
// reduce -> per-CTA partial (max, sumexp, argmax) into g_part.
__device__ __forceinline__ void l_combine(
    int cc, int tid, const float* __restrict__ b_out, float lv[BB][8])
{
    if (tid < BB * 8) {
        const int b = tid >> 3, vs = tid & 7;
        const int vabs = cc * 8 + vs;
        float val = lv[b][vs] + b_out[vabs];

        float m = val; int mi = vabs;
#pragma unroll
        for (int d = 4; d > 0; d >>= 1) {
            float m2 = __shfl_xor_sync(0xffffffffu, m, d, 8);
            int   i2 = __shfl_xor_sync(0xffffffffu, mi, d, 8);
            if (m2 > m || (m2 == m && i2 < mi)) { m = m2; mi = i2; }
        }
        float s = expf(val - m);
#pragma unroll
        for (int d = 4; d > 0; d >>= 1)
            s += __shfl_xor_sync(0xffffffffu, s, d, 8);

        if (vs == 0) g_part[b][cc] = make_float4(m, s, (float)mi, 0.f);
    }
}

// ============================================================================
// Merge: warps 0-15 merge the 128 partials per batch (bitwise-deterministic);
// CTA 0 writes tokens + score.
// ============================================================================
__device__ __forceinline__ void merge_phase(
    int cc, int wid, int lane, int t,
    float* __restrict__ out, int* s_tok, int* s_nb)
{
#pragma unroll
    for (int bi = 0; bi < 2; bi++) {
        const int b = wid * 2 + bi;
        float4 q = g_part[b][lane];
        float m = q.x, s = q.y; int mi = (int)q.z;
#pragma unroll
        for (int r = 1; r < 4; r++) {
            float4 p = g_part[b][lane + 32 * r];
            pmerge(m, s, mi, p.x, p.y, (int)p.z);
        }
#pragma unroll
        for (int d = 16; d > 0; d >>= 1) {
            float m2 = __shfl_xor_sync(0xffffffffu, m, d);
            float s2 = __shfl_xor_sync(0xffffffffu, s, d);
            int   i2 = __shfl_xor_sync(0xffffffffu, mi, d);
            pmerge(m, s, mi, m2, s2, i2);
        }
        if (lane == 0) {
            const int nb = (mi != 0);
            s_nb[b] = nb;
            s_tok[b] = nb ? mi : 0;   // blank-step LSTM result is discarded
            if (cc == 0) {
                out[(size_t)b * TT + t] = nb ? (float)mi : 0.0f;
                if (nb) g_score[b] += -logf(s);  // logp at argmax
            }
        }
    }
}

// ============================================================================
// G halves (term-split across warps): 16 warps each, warp = pass(2) x bg(8),
// acc[4][10]. gx: E[tok]·W_ih (warps 0-15). gh: h·W_hh (warps 16-31).
// ============================================================================
__device__ __forceinline__ void g_half(
    int cc, int wl, int lane, int rp, int isH,
    const float* __restrict__ E, const float* __restrict__ W,
    float* sg, const int* s_tok)
{
    const int j0 = cc * 5;
    const int pass = wl >> 3;           // 0: gates i,f   1: gates g,o
    const int b0 = (wl & 7) * 4;

    float acc[4][10];
#pragma unroll
    for (int i = 0; i < 4; i++)
#pragma unroll
        for (int o = 0; o < 10; o++) acc[i][o] = 0.f;

    int xo[4];
#pragma unroll
    for (int i = 0; i < 4; i++) xo[i] = isH ? 0 : s_tok[b0 + i] * DD;

#pragma unroll 1
    for (int kc = 0; kc < DD; kc += 128) {
        const int k = kc + lane * 4;
        float4 av[4];
#pragma unroll
        for (int i = 0; i < 4; i++) {
            av[i] = isH ? *(const float4*)(&g_hbuf[rp][b0 + i][k])
                        : *(const float4*)(E + (size_t)xo[i] + k);
        }
#pragma unroll
        for (int o = 0; o < 10; o++) {
            const int row = (pass * 2 + o / 5) * DD + j0 + (o % 5);
            float4 w = *(const float4*)(W + (size_t)row * DD + k);
#pragma unroll
            for (int i = 0; i < 4; i++) {
                float a = acc[i][o];
                a = fmaf(av[i].x, w.x, a); a = fmaf(av[i].y, w.y, a);
                a = fmaf(av[i].z, w.z, a); a = fmaf(av[i].w, w.w, a);
                acc[i][o] = a;
            }
        }
    }
#pragma unroll
    for (int i = 0; i < 4; i++)
#pragma unroll
        for (int o = 0; o < 10; o++) {
            float r = wred(acc[i][o]);
            if (lane == 0) sg[(b0 + i) * 20 + pass * 10 + o] = r;
        }
}

// ============================================================================
// Pointwise LSTM update: warps 0-7, lanes 0-19 -> (batch, j) pairs.
// ============================================================================
__device__ __forceinline__ void pointwise(
    int cc, int wid, int lane, int rp,
    const float* __restrict__ b_lstm, const float* sgx, const float* sgh,
    const int* s_nb)
{
    const int j0 = cc * 5;
    if (wid < 8 && lane < 20) {
        const int i = lane / 5, jj = lane - i * 5;
        const int b = wid * 4 + i;
        const int j = j0 + jj;
        if (s_nb[b]) {
            float gi = sgx[b * 20 + jj]      + sgh[b * 20 + jj]      + b_lstm[j];
            float gf = sgx[b * 20 + 5 + jj]  + sgh[b * 20 + 5 + jj]  + b_lstm[DD + j];
            float gg = sgx[b * 20 + 10 + jj] + sgh[b * 20 + 10 + jj] + b_lstm[2 * DD + j];
            float go = sgx[b * 20 + 15 + jj] + sgh[b * 20 + 15 + jj] + b_lstm[3 * DD + j];
            float cn = sigf(gf) * g_c[b][j] + sigf(gi) * tanhf(gg);
            float hn = sigf(go) * tanhf(cn);
            g_c[b][j] = cn;
            g_hbuf[rp ^ 1][b][j] = hn;
        } else {
            g_hbuf[rp ^ 1][b][j] = g_hbuf[rp][b][j];
        }
    }
}

// ============================================================================
// Persistent kernel: init -> prime -> 1000 x { Z | L | merge||gh, gx, pw }
// ============================================================================
__global__ void __launch_bounds__(NT, 1)
rnnt_decode_kernel(const float* __restrict__ tn,     const float* __restrict__ E,
                   const float* __restrict__ W_ih,   const float* __restrict__ W_hh,
                   const float* __restrict__ b_lstm, const float* __restrict__ W_tn,
                   const float* __restrict__ W_pn,   const float* __restrict__ b_joint,
                   const float* __restrict__ W_out,  const float* __restrict__ b_out,
                   float* __restrict__ out)
{
    __shared__ float zp[2][BB][5];
    __shared__ float lv[BB][8];
    __shared__ float sgx[BB * 20];
    __shared__ float sgh[BB * 20];
    __shared__ int   s_tok[BB];
    __shared__ int   s_nb[BB];

    const int cc   = blockIdx.x;
    const int tid  = threadIdx.x;
    const int lane = tid & 31;
    const int wid  = tid >> 5;

    // ---- per-launch state init (deterministic across graph replays) ----
    for (int i = cc * NT + tid; i < BB * DD; i += NB * NT) {
        (&g_hbuf[0][0][0])[i] = 0.f;
        (&g_c[0][0])[i]       = 0.f;
    }
    if (cc == 0 && tid < BB) g_score[tid] = 0.f;
    grid_barrier();

    // ---- priming step: h,c = lstm(E[BLANK], 0, 0); h-half is 0 (h==0) ----
    if (wid == 0 && lane < BB) { s_tok[lane] = 0; s_nb[lane] = 1; }
    __syncthreads();
    int par = 0;
    if (wid < 16) g_half(cc, wid,      lane, par, 0, E, W_ih, sgx, s_tok);
    else          g_half(cc, wid - 16, lane, par, 1, E, W_hh, sgh, s_tok);
    __syncthreads();
    pointwise(cc, wid, lane, par, b_lstm, sgx, sgh, s_nb);
    par = 1;
    grid_barrier();

    // ---- sequential decode ----
    for (int t = 0; t < TT; t++) {
        // Phase A: joint projection (term-split), combine, publish g_z
        z_phase(cc, wid, lane, t, par, tn, W_tn, W_pn, zp);
        __syncthreads();
        z_combine(cc, tid, b_joint, zp);
        grid_barrier();

        // Phase B: logits GEMV (v-split) + 8-wide softmax partials
        l_phase(cc, wid, lane, W_out, lv);
        __syncthreads();
        l_combine(cc, tid, b_out, lv);
        grid_barrier();

        // Phase C: [warps 0-15: merge -> gx] || [warps 16-31: gh], then pw
        if (t < TT - 1) {
            if (wid < 16) {
                merge_phase(cc, wid, lane, t, out, s_tok, s_nb);
                asm volatile("bar.sync 1, 512;" ::: "memory");  // order merge->gx
                g_half(cc, wid, lane, par, 0, E, W_ih, sgx, s_tok);
            } else {
                g_half(cc, wid - 16, lane, par, 1, E, W_hh, sgh, s_tok);
            }
            __syncthreads();
            pointwise(cc, wid, lane, par, b_lstm, sgx, sgh, s_nb);
            par ^= 1;
            grid_barrier();
        } else {
            if (wid < 16) merge_phase(cc, wid, lane, t, out, s_tok, s_nb);
            __syncthreads();
        }
    }

    // ---- epilogue: scores + mean(exp(score)) (CTA 0 owns g_score) ----
    if (cc == 0) {
        if (tid < BB) out[(size_t)BB * TT + tid] = g_score[tid];
        if (tid == 0) {
            float s = 0.f;
            for (int b = 0; b < BB; b++) s += expf(g_score[b]);
            out[(size_t)BB * TT + BB] = s / (float)BB;
        }
    }
}

extern "C" void kernel_launch(void* const* d_in, const int* in_sizes, int n_in,
                              void* d_out, int out_size)
{
    (void)in_sizes; (void)n_in; (void)out_size;
    const float* tn      = (const float*)d_in[0];
    const float* E       = (const float*)d_in[1];
    const float* W_ih    = (const float*)d_in[2];
    const float* W_hh    = (const float*)d_in[3];
    const float* b_lstm  = (const float*)d_in[4];
    const float* W_tn    = (const float*)d_in[5];
    const float* W_pn    = (const float*)d_in[6];
    const float* b_joint = (const float*)d_in[7];
    const float* W_out   = (const float*)d_in[8];
    const float* b_out   = (const float*)d_in[9];
    float* out = (float*)d_out;

    rnnt_decode_kernel<<<NB, NT>>>(tn, E, W_ih, W_hh, b_lstm,
                                   W_tn, W_pn, b_joint, W_out, b_out, out);
}